// round 16
// baseline (speedup 1.0000x reference)
#include <cuda_runtime.h>

// PositionalEncodingLayer: out[b,t,d] = X[b,t,d] + pe[t,d]
//   pe[t, 2i]   = sin(t / 10000^(2i/d))
//   pe[t, 2i+1] = cos(t / 10000^(2i/d))
// B=8, T=4096, D=1024, fp32.
//
// CONVERGED FINAL FORM (identical bytes measured four times):
//   R2:  bench 45.34us, kernel 38.75us
//   R12: bench 45.70us, kernel 37.86us
//   R13: bench 45.22us, kernel 37.63us  (session best)
//   R15: bench 45.38us, kernel 37.70us
// Distribution: bench mean 45.41us, sigma ~0.2us. Inter-form differences
// among tuned variants (<0.4us) are below single-binary run-to-run noise.
// Wall-clock effective BW = 268MB / 37.7us = 7.1 TB/s = 89% of spec:
// pinned at the mixed read+write HBM3e turnaround ceiling.
//
// Session evidence — every structural lever tested and falsified:
//  - R4: occupancy (occ 41->62% moved DRAM only 68->70%, bench flat)
//  - R6: persistence (one-wave grid-stride regressed to 53.4us; per-SM CTA
//        injection with front-batched loads IS the latency-hiding mechanism)
//  - R9: joint MLP8 x occupancy-cap (regressed to 46.5us; reg-cap squeeze)
// Traffic is irreducible: 128MB in + 128MB out, pe computed in-register
// (fma pipe 6% busy); the LTS/DRAM ceiling is access-mechanism-independent,
// ruling out TMA/hint variants. The residual ~11% to spec is HBM rw bus
// turnaround — below the SASS abstraction.
//
// Structure: grid=4096 (one row per CTA), 256 threads (one float4 chunk per
// thread). All 8 batch-plane loads front-batched (MLP=8) so the ~600cy DRAM
// latency overlaps the two sincosf; add + streaming stores follow.

constexpr int Bn  = 8;
constexpr int Tn  = 4096;
constexpr int Dn  = 1024;
constexpr int C4  = Dn / 4;            // 256 float4 chunks per row
constexpr int PLANE4 = Tn * C4;        // float4 per batch plane (1,048,576)

__global__ __launch_bounds__(C4)
void pe_add_kernel(const float4* __restrict__ X, float4* __restrict__ O)
{
    const int j = threadIdx.x;             // column chunk: cols 4j..4j+3
    const int t = blockIdx.x;              // row
    const int idx = t * C4 + j;            // fits in int32 (max 8M)

    // Issue all 8 loads up front — independent, front-batched MLP.
    float4 x[Bn];
    #pragma unroll
    for (int b = 0; b < Bn; ++b)
        x[b] = __ldcs(&X[idx + b * PLANE4]);

    // pe for this thread's 4 columns (pair 2j -> sin/cos, pair 2j+1 -> sin/cos)
    // inv_freq_i = 10000^(-2i/D) = exp2(-i * 2*log2(10000)/D)
    const float k  = 0.02595256306250292f; // 2*log2(10000)/1024
    const float i0 = (float)(2 * j);
    const float f0 = exp2f(-i0 * k);
    const float f1 = exp2f(-(i0 + 1.0f) * k);
    float s0, c0, s1, c1;
    sincosf((float)t * f0, &s0, &c0);
    sincosf((float)t * f1, &s1, &c1);

    #pragma unroll
    for (int b = 0; b < Bn; ++b) {
        float4 v = x[b];
        v.x += s0; v.y += c0; v.z += s1; v.w += c1;
        __stcs(&O[idx + b * PLANE4], v);
    }
}

extern "C" void kernel_launch(void* const* d_in, const int* in_sizes, int n_in,
                              void* d_out, int out_size)
{
    (void)in_sizes; (void)n_in; (void)out_size;
    const float4* X = (const float4*)d_in[0];
    float4*       O = (float4*)d_out;
    pe_add_kernel<<<Tn, C4>>>(X, O);
}